// round 3
// baseline (speedup 1.0000x reference)
#include <cuda_runtime.h>

// out[b,p,:] = { c1*c2*c3, c0*c1, c0*c1*c2, c0*c1*c2*c3 }, c_i = cos(patches[b,p,i]).
// RZ params provably do not affect the output (unit phases cancel in |amp|^2).
//
// R3: single wave (1024 CTAs, ~7/SM) + 2 independent front-batched float4
// loads per thread + no per-item predication (exact tiling of 524288 items).

#define ITEMS 2
#define TPB   256

__global__ __launch_bounds__(TPB) void quantum_patch_kernel(
    const float4* __restrict__ in,
    float4* __restrict__ out) {
    int base = blockIdx.x * (TPB * ITEMS) + threadIdx.x;

    // Front-batched independent loads (MLP_p1 = 2 per thread).
    float4 x0 = in[base];
    float4 x1 = in[base + TPB];

    float4 o0, o1;
    {
        float c0 = __cosf(x0.x), c1 = __cosf(x0.y), c2 = __cosf(x0.z), c3 = __cosf(x0.w);
        float c12 = c1 * c2;
        float c123 = c12 * c3;
        o0.x = c123;
        o0.y = c0 * c1;
        o0.z = c0 * c12;
        o0.w = c0 * c123;
    }
    {
        float c0 = __cosf(x1.x), c1 = __cosf(x1.y), c2 = __cosf(x1.z), c3 = __cosf(x1.w);
        float c12 = c1 * c2;
        float c123 = c12 * c3;
        o1.x = c123;
        o1.y = c0 * c1;
        o1.z = c0 * c12;
        o1.w = c0 * c123;
    }

    out[base]       = o0;
    out[base + TPB] = o1;
}

// Fallback with bounds checks in case element count isn't an exact multiple.
__global__ __launch_bounds__(TPB) void quantum_patch_kernel_guarded(
    const float4* __restrict__ in,
    float4* __restrict__ out,
    int n_patches) {
    int i = blockIdx.x * TPB + threadIdx.x;
    if (i < n_patches) {
        float4 x = in[i];
        float c0 = __cosf(x.x), c1 = __cosf(x.y), c2 = __cosf(x.z), c3 = __cosf(x.w);
        float c12 = c1 * c2;
        float c123 = c12 * c3;
        float4 o;
        o.x = c123;
        o.y = c0 * c1;
        o.z = c0 * c12;
        o.w = c0 * c123;
        out[i] = o;
    }
}

extern "C" void kernel_launch(void* const* d_in, const int* in_sizes, int n_in,
                              void* d_out, int out_size) {
    const float4* patches = (const float4*)d_in[0];   // (256, 2048, 4) f32
    float4* out = (float4*)d_out;                     // (256, 8192) f32 — same layout
    int n_patches = in_sizes[0] / 4;                  // 524288
    const int per_block = TPB * ITEMS;                // 512
    if (n_patches % per_block == 0) {
        quantum_patch_kernel<<<n_patches / per_block, TPB>>>(patches, out);  // 1024 CTAs
    } else {
        quantum_patch_kernel_guarded<<<(n_patches + TPB - 1) / TPB, TPB>>>(patches, out, n_patches);
    }
}

// round 4
// speedup vs baseline: 1.0386x; 1.0386x over previous
#include <cuda_runtime.h>

// out[b,p,:] = { c1*c2*c3, c0*c1, c0*c1*c2, c0*c1*c2*c3 }, c_i = cos(patches[b,p,i]).
// RZ params provably do not affect the output (unit phases cancel in |amp|^2).
//
// R4: cosine computed on the FMA pipe (Taylor poly + 2x double-angle) instead
// of MUFU, which the R1-R3 evidence suggests is the binding (hidden) pipe.

#define ITEMS 2
#define TPB   256

// cos(x) for |x| <= ~8, pure FMA-pipe. s = x/4; P = cos(s) (7-term Taylor,
// rem < 2e-7 at |s|=2); then two double-angle steps: cos(2a) = 2cos^2(a)-1.
__device__ __forceinline__ float cos_fma(float x) {
    float s = x * 0.25f;
    float u = s * s;
    float p = fmaf(u, 1.0f / 479001600.0f, -1.0f / 3628800.0f);
    p = fmaf(u, p,  1.0f / 40320.0f);
    p = fmaf(u, p, -1.0f / 720.0f);
    p = fmaf(u, p,  1.0f / 24.0f);
    p = fmaf(u, p, -0.5f);
    p = fmaf(u, p,  1.0f);            // cos(x/4)
    float t = p * p;
    float ch = fmaf(2.0f, t, -1.0f);  // cos(x/2)
    float t2 = ch * ch;
    return fmaf(2.0f, t2, -1.0f);     // cos(x)
}

__device__ __forceinline__ float4 qpatch(float4 x) {
    float c0 = cos_fma(x.x);
    float c1 = cos_fma(x.y);
    float c2 = cos_fma(x.z);
    float c3 = cos_fma(x.w);
    float c12  = c1 * c2;
    float c123 = c12 * c3;
    float4 o;
    o.x = c123;
    o.y = c0 * c1;
    o.z = c0 * c12;
    o.w = c0 * c123;
    return o;
}

__global__ __launch_bounds__(TPB) void quantum_patch_kernel(
    const float4* __restrict__ in,
    float4* __restrict__ out) {
    int base = blockIdx.x * (TPB * ITEMS) + threadIdx.x;
    float4 x0 = in[base];
    float4 x1 = in[base + TPB];
    out[base]       = qpatch(x0);
    out[base + TPB] = qpatch(x1);
}

__global__ __launch_bounds__(TPB) void quantum_patch_kernel_guarded(
    const float4* __restrict__ in,
    float4* __restrict__ out,
    int n_patches) {
    int i = blockIdx.x * TPB + threadIdx.x;
    if (i < n_patches) out[i] = qpatch(in[i]);
}

extern "C" void kernel_launch(void* const* d_in, const int* in_sizes, int n_in,
                              void* d_out, int out_size) {
    const float4* patches = (const float4*)d_in[0];   // (256, 2048, 4) f32
    float4* out = (float4*)d_out;                     // (256, 8192) f32 — same layout
    int n_patches = in_sizes[0] / 4;                  // 524288
    const int per_block = TPB * ITEMS;                // 512
    if (n_patches % per_block == 0) {
        quantum_patch_kernel<<<n_patches / per_block, TPB>>>(patches, out);  // 1024 CTAs
    } else {
        quantum_patch_kernel_guarded<<<(n_patches + TPB - 1) / TPB, TPB>>>(patches, out, n_patches);
    }
}